// round 1
// baseline (speedup 1.0000x reference)
#include <cuda_runtime.h>
#include <cuda_bf16.h>
#include <mma.h>
#include <cstdint>

using namespace nvcuda;

#define NROWS 4096
#define DIM   512
#define NCLS  100000
#define S_SCALE 30.0f
#define MARGIN  0.4f

// ---------------- scratch (module-static device memory: allowed) ------------
__device__ __nv_bfloat16 g_WB[(size_t)NCLS * DIM];   // bf16 copy of W
__device__ __nv_bfloat16 g_xn[(size_t)NROWS * DIM];  // bf16 normalized x
__device__ float g_rowsum[NROWS];                    // sum_j exp(s*wf[i,j])
__device__ float g_target[NROWS];                    // exact fp32 wf[i, y_i]

// ---------------- kernel 1: W fp32 -> bf16 ----------------------------------
__global__ void convert_w_kernel(const float* __restrict__ W) {
    size_t i = (size_t)blockIdx.x * blockDim.x + threadIdx.x;   // float4 index
    const size_t total = (size_t)NCLS * DIM / 4;
    if (i >= total) return;
    float4 v = reinterpret_cast<const float4*>(W)[i];
    __nv_bfloat162 lo = __floats2bfloat162_rn(v.x, v.y);
    __nv_bfloat162 hi = __floats2bfloat162_rn(v.z, v.w);
    reinterpret_cast<__nv_bfloat162*>(g_WB)[2 * i + 0] = lo;
    reinterpret_cast<__nv_bfloat162*>(g_WB)[2 * i + 1] = hi;
}

// ---------------- kernel 2: normalize x, exact target, zero rowsum ----------
__device__ __forceinline__ float block_reduce_128(float v, float* sbuf, int tid) {
    #pragma unroll
    for (int o = 16; o > 0; o >>= 1) v += __shfl_xor_sync(0xffffffffu, v, o);
    if ((tid & 31) == 0) sbuf[tid >> 5] = v;
    __syncthreads();
    float r = sbuf[0] + sbuf[1] + sbuf[2] + sbuf[3];
    __syncthreads();
    return r;
}

__global__ void norm_target_kernel(const float* __restrict__ x,
                                   const int* __restrict__ labels_raw,
                                   const float* __restrict__ W) {
    __shared__ float sbuf[4];
    int row = blockIdx.x, tid = threadIdx.x;
    const float* xr = x + (size_t)row * DIM;
    float v[4];
    float ss = 0.f;
    #pragma unroll
    for (int j = 0; j < 4; j++) { v[j] = xr[tid + 128 * j]; ss += v[j] * v[j]; }
    ss = block_reduce_128(ss, sbuf, tid);
    float inv = rsqrtf(ss);
    #pragma unroll
    for (int j = 0; j < 4; j++)
        g_xn[(size_t)row * DIM + tid + 128 * j] = __float2bfloat16(v[j] * inv);

    // labels may be int64 (reference dtype) or int32 (jax canonicalization).
    // For int64 little-endian labels < 2^31, every odd int32 word is 0.
    bool is64 = (labels_raw[1] == 0 && labels_raw[3] == 0 &&
                 labels_raw[5] == 0 && labels_raw[7] == 0);
    int lab = is64 ? labels_raw[2 * row] : labels_raw[row];
    const float* w = W + (size_t)lab * DIM;
    float dot = 0.f;
    #pragma unroll
    for (int j = 0; j < 4; j++) dot += v[j] * w[tid + 128 * j];
    dot = block_reduce_128(dot, sbuf, tid);
    if (tid == 0) {
        g_target[row] = dot * inv;
        g_rowsum[row] = 0.f;
    }
}

// ---------------- kernel 3: fused GEMM + exp row-sum -------------------------
// C_tile[m,n] = sum_k xn[m,k] * W[n,k]   (NT gemm, both K-major)
// Block: 512 threads (16 warps), tile 128(M) x 128(N) x 32(K).
// Warp layout: wm = wid & 3 (32-row strip), wn = wid >> 2 (32-col strip),
// each warp owns 2x2 wmma 16x16x16 fragments.
#define BM 128
#define BN 128
#define BK 32
#define APITCH 48   // bf16 elements; 96B row pitch (16B-aligned, skewed)

__global__ void __launch_bounds__(512)
gemm_exp_kernel() {
    __shared__ __align__(16) __nv_bfloat16 As[BM * APITCH];
    __shared__ __align__(16) __nv_bfloat16 Bs[BN * APITCH];
    __shared__ float s_rowsum[BM];
    __shared__ __align__(16) float scratch[16 * 16 * 20];  // per-warp 16x20 fp32

    const int tid  = threadIdx.x;
    const int wid  = tid >> 5;
    const int lane = tid & 31;
    const int wm   = wid & 3;
    const int wn   = wid >> 2;
    const int bm   = blockIdx.x;   // 0..31 row tiles (fast-varying -> L2 reuse of B)
    const int bn   = blockIdx.y;   // 0..781 col tiles

    if (tid < BM) s_rowsum[tid] = 0.f;

    wmma::fragment<wmma::accumulator, 16, 16, 16, float> acc[2][2];
    #pragma unroll
    for (int fm = 0; fm < 2; fm++)
        #pragma unroll
        for (int fn = 0; fn < 2; fn++)
            wmma::fill_fragment(acc[fm][fn], 0.0f);

    // load assignment: 512 threads x one 16B vector per tile operand
    const int arow = tid >> 2;          // 0..127
    const int acol = (tid & 3) * 8;     // 0,8,16,24
    const size_t a_base = ((size_t)(bm * BM + arow)) * DIM + acol;
    const int    nrow_g = bn * BN + arow;
    const size_t b_base = (size_t)nrow_g * DIM + acol;
    const bool   bvalid = (nrow_g < NCLS);

    for (int k0 = 0; k0 < DIM; k0 += BK) {
        __syncthreads();   // previous iter's reads done (also covers s_rowsum init)
        uint4 av = *reinterpret_cast<const uint4*>(g_xn + a_base + k0);
        *reinterpret_cast<uint4*>(&As[arow * APITCH + acol]) = av;
        uint4 bv = make_uint4(0u, 0u, 0u, 0u);
        if (bvalid) bv = *reinterpret_cast<const uint4*>(g_WB + b_base + k0);
        *reinterpret_cast<uint4*>(&Bs[arow * APITCH + acol]) = bv;
        __syncthreads();

        #pragma unroll
        for (int kk = 0; kk < BK; kk += 16) {
            wmma::fragment<wmma::matrix_a, 16, 16, 16, __nv_bfloat16, wmma::row_major> af[2];
            wmma::fragment<wmma::matrix_b, 16, 16, 16, __nv_bfloat16, wmma::col_major> bf[2];
            #pragma unroll
            for (int fm = 0; fm < 2; fm++)
                wmma::load_matrix_sync(af[fm], &As[(wm * 32 + fm * 16) * APITCH + kk], APITCH);
            #pragma unroll
            for (int fn = 0; fn < 2; fn++)
                wmma::load_matrix_sync(bf[fn], &Bs[(wn * 32 + fn * 16) * APITCH + kk], APITCH);
            #pragma unroll
            for (int fm = 0; fm < 2; fm++)
                #pragma unroll
                for (int fn = 0; fn < 2; fn++)
                    wmma::mma_sync(acc[fm][fn], af[fm], bf[fn], acc[fm][fn]);
        }
    }
    __syncthreads();

    // epilogue: exp + per-row partial sums (column-masked for C=100000)
    float* sc = &scratch[wid * 320];
    #pragma unroll
    for (int fm = 0; fm < 2; fm++) {
        #pragma unroll
        for (int fn = 0; fn < 2; fn++) {
            wmma::store_matrix_sync(sc, acc[fm][fn], 20, wmma::mem_row_major);
            __syncwarp();
            const int r    = lane >> 1;
            const int half = lane & 1;
            const int ng0  = bn * BN + wn * 32 + fn * 16 + half * 8;
            float sum = 0.f;
            #pragma unroll
            for (int c = 0; c < 8; c++) {
                float v = sc[r * 20 + half * 8 + c];
                if (ng0 + c < NCLS) sum += __expf(S_SCALE * v);
            }
            atomicAdd(&s_rowsum[wm * 32 + fm * 16 + r], sum);
            __syncwarp();
        }
    }
    __syncthreads();
    if (tid < BM) atomicAdd(&g_rowsum[bm * BM + tid], s_rowsum[tid]);
}

// ---------------- kernel 4: finalize -----------------------------------------
__global__ void finalize_kernel(float* __restrict__ out) {
    __shared__ double sd[256];
    int tid = threadIdx.x;
    double local = 0.0;
    for (int i = tid; i < NROWS; i += 256) {
        float t   = g_target[i];
        float num = S_SCALE * (t - MARGIN);
        float denom = expf(num) + g_rowsum[i] - expf(S_SCALE * t);
        local += (double)num - log((double)denom);
    }
    sd[tid] = local;
    __syncthreads();
    for (int s = 128; s > 0; s >>= 1) {
        if (tid < s) sd[tid] += sd[tid + s];
        __syncthreads();
    }
    if (tid == 0) out[0] = (float)(-sd[0] / (double)NROWS);
}

// ---------------- launch ------------------------------------------------------
extern "C" void kernel_launch(void* const* d_in, const int* in_sizes, int n_in,
                              void* d_out, int out_size) {
    const float* x      = (const float*)d_in[0];
    const int*   labels = (const int*)d_in[1];   // width auto-detected on device
    const float* W      = (const float*)d_in[2];
    float* out = (float*)d_out;

    {   // W fp32 -> bf16
        size_t total4 = (size_t)NCLS * DIM / 4;
        int blocks = (int)((total4 + 255) / 256);
        convert_w_kernel<<<blocks, 256>>>(W);
    }
    norm_target_kernel<<<NROWS, 128>>>(x, labels, W);
    {
        dim3 grid(NROWS / BM, (NCLS + BN - 1) / BN);   // (32, 782)
        gemm_exp_kernel<<<grid, 512>>>();
    }
    finalize_kernel<<<1, 256>>>(out);
}

// round 4
// speedup vs baseline: 1.5523x; 1.5523x over previous
#include <cuda_runtime.h>
#include <cuda_bf16.h>
#include <mma.h>
#include <cstdint>

using namespace nvcuda;

#define NROWS 4096
#define DIM   512
#define NCLS  100000
#define NBN   391            // ceil(100000/256)
#define S_SCALE 30.0f
#define MARGIN  0.4f

// ---------------- scratch (module-static device memory: allowed) ------------
__device__ __align__(128) __nv_bfloat16 g_WB[(size_t)NCLS * DIM];   // bf16 W
__device__ __align__(128) __nv_bfloat16 g_xn[(size_t)NROWS * DIM];  // bf16 xn
__device__ float g_rowsum[NROWS];
__device__ float g_target[NROWS];

// ---------------- tiny PTX helpers (all sm_80-era, safe on sm_103) ----------
__device__ __forceinline__ uint32_t smem_u32(const void* p) {
    uint32_t a;
    asm("{ .reg .u64 t; cvta.to.shared.u64 t, %1; cvt.u32.u64 %0, t; }" : "=r"(a) : "l"(p));
    return a;
}
#define CP_ASYNC16(dst, src) \
    asm volatile("cp.async.cg.shared.global [%0], [%1], 16;" :: "r"(dst), "l"(src) : "memory")
#define CP_COMMIT()  asm volatile("cp.async.commit_group;" ::: "memory")
#define CP_WAIT1()   asm volatile("cp.async.wait_group 1;" ::: "memory")

// ---------------- tiling ------------------------------------------------------
#define BM 128
#define BN 256
#define BK 64
#define APITCH 520          // A row stride (elems): 1040B = 260 words == 4 mod 32
#define BPITCH 72           // B row stride (elems): 144B  = 36 words  == 4 mod 32

#define A_BYTES       (BM * APITCH * 2)              // 133120
#define B_STAGE_BYTES (BN * BPITCH * 2)              // 36864
#define B_OFF         A_BYTES
#define SCR_OFF       (B_OFF + 2 * B_STAGE_BYTES)    // 206848
#define SMEM_BYTES    (SCR_OFF + 8 * 320 * 4)        // 217088

// ======================= kernel 1: W fp32 -> bf16 ============================
__global__ void convert_w_kernel(const float* __restrict__ W) {
    size_t i = (size_t)blockIdx.x * blockDim.x + threadIdx.x;
    const size_t total = (size_t)NCLS * DIM / 4;
    if (i >= total) return;
    float4 v = reinterpret_cast<const float4*>(W)[i];
    reinterpret_cast<__nv_bfloat162*>(g_WB)[2*i+0] = __floats2bfloat162_rn(v.x, v.y);
    reinterpret_cast<__nv_bfloat162*>(g_WB)[2*i+1] = __floats2bfloat162_rn(v.z, v.w);
}

// ======================= kernel 2: normalize + exact target ==================
__device__ __forceinline__ float block_reduce_128(float v, float* sbuf, int tid) {
    #pragma unroll
    for (int o = 16; o > 0; o >>= 1) v += __shfl_xor_sync(0xffffffffu, v, o);
    if ((tid & 31) == 0) sbuf[tid >> 5] = v;
    __syncthreads();
    float r = sbuf[0] + sbuf[1] + sbuf[2] + sbuf[3];
    __syncthreads();
    return r;
}

__global__ void norm_target_kernel(const float* __restrict__ x,
                                   const int* __restrict__ labels_raw,
                                   const float* __restrict__ W) {
    __shared__ float sbuf[4];
    int row = blockIdx.x, tid = threadIdx.x;
    const float* xr = x + (size_t)row * DIM;
    float v[4]; float ss = 0.f;
    #pragma unroll
    for (int j = 0; j < 4; j++) { v[j] = xr[tid + 128*j]; ss += v[j]*v[j]; }
    ss = block_reduce_128(ss, sbuf, tid);
    float inv = rsqrtf(ss);
    #pragma unroll
    for (int j = 0; j < 4; j++)
        g_xn[(size_t)row * DIM + tid + 128*j] = __float2bfloat16(v[j] * inv);

    // labels: int64 (odd words zero) or int32
    bool is64 = (labels_raw[1] == 0 && labels_raw[3] == 0 &&
                 labels_raw[5] == 0 && labels_raw[7] == 0);
    int lab = is64 ? labels_raw[2*row] : labels_raw[row];
    const float* w = W + (size_t)lab * DIM;
    float dot = 0.f;
    #pragma unroll
    for (int j = 0; j < 4; j++) dot += v[j] * w[tid + 128*j];
    dot = block_reduce_128(dot, sbuf, tid);
    if (tid == 0) { g_target[row] = dot * inv; g_rowsum[row] = 0.f; }
}

// ======================= kernel 3: pipelined HMMA GEMM + exp rowsum ==========
// grid (32, 4): blockIdx.x = row strip bm (A resident in SMEM),
// blockIdx.y = g; CTA handles bn = g, g+4, g+8, ...
// 256 threads / 8 warps; warp grid 2(m) x 4(n); warp tile 64x64.
// 2-stage cp.async pipeline over K chunks of 64.
__device__ __forceinline__ void issue_b_chunk(uint32_t bs_dst, int bn, int k0, int tid) {
    // 256 rows x 64 bf16 (=128B = 8 x 16B vectors per row) -> 2048 vectors
    #pragma unroll
    for (int i = 0; i < 8; i++) {
        int v = tid + 256 * i;
        int r = v >> 3, kv = v & 7;             // row 0..255, kvec 0..7
        int grow = bn * BN + r; if (grow >= NCLS) grow = NCLS - 1;
        const void* src = g_WB + ((size_t)grow * DIM + k0 + kv * 8);
        CP_ASYNC16(bs_dst + r * (BPITCH * 2) + kv * 16, src);
    }
}

__global__ void __launch_bounds__(256, 1) gemm_exp_kernel() {
    extern __shared__ __align__(16) char smem[];
    __nv_bfloat16* As = reinterpret_cast<__nv_bfloat16*>(smem);
    float* scratch = reinterpret_cast<float*>(smem + SCR_OFF);
    const uint32_t sb = smem_u32(smem);

    const int tid = threadIdx.x, wid = tid >> 5, lane = tid & 31;
    const int wm = wid & 1, wn = wid >> 1;
    const int bm = blockIdx.x, g = blockIdx.y;
    const int ntiles = (NBN - g + 3) >> 2;
    const int total = ntiles * 8;               // K chunks of 64 across all tiles

    // ---- A strip load (once) ----
    const __nv_bfloat16* xa = g_xn + (size_t)bm * BM * DIM;
    #pragma unroll 4
    for (int i = 0; i < 32; i++) {
        int v = tid + 256 * i;                  // 8192 vectors
        int r = v >> 6, kv = v & 63;
        CP_ASYNC16(sb + r * (APITCH * 2) + kv * 16,
                   xa + ((size_t)r * DIM + kv * 8));
    }
    CP_COMMIT();
    // ---- prologue: B chunk 0 ----
    issue_b_chunk(sb + B_OFF, g, 0, tid);
    CP_COMMIT();

    wmma::fragment<wmma::accumulator, 16, 16, 16, float> acc[4][4];
    #pragma unroll
    for (int fm = 0; fm < 4; fm++)
        #pragma unroll
        for (int fn = 0; fn < 4; fn++)
            wmma::fill_fragment(acc[fm][fn], 0.0f);

    float rsum[4] = {0.f, 0.f, 0.f, 0.f};
    const int r2 = lane >> 1, half = lane & 1;

    for (int j = 0; j < total; j++) {
        __syncthreads();                        // stage (j+1)&1 free (chunk j-1 consumed)
        int jn = j + 1;
        if (jn < total) {
            int bn = g + 4 * (jn >> 3);
            issue_b_chunk(sb + B_OFF + (jn & 1) * B_STAGE_BYTES, bn, (jn & 7) * BK, tid);
        }
        CP_COMMIT();
        CP_WAIT1();                             // chunk j (and A) arrived
        __syncthreads();

        // ---- compute chunk j ----
        const __nv_bfloat16* bs = reinterpret_cast<__nv_bfloat16*>(
            smem + B_OFF + (j & 1) * B_STAGE_BYTES);
        const int k0 = (j & 7) * BK;
        #pragma unroll
        for (int kk = 0; kk < BK; kk += 16) {
            wmma::fragment<wmma::matrix_a, 16, 16, 16, __nv_bfloat16, wmma::row_major> af[4];
            wmma::fragment<wmma::matrix_b, 16, 16, 16, __nv_bfloat16, wmma::col_major> bf[4];
            #pragma unroll
            for (int fm = 0; fm < 4; fm++)
                wmma::load_matrix_sync(af[fm], &As[(wm*64 + fm*16) * APITCH + k0 + kk], APITCH);
            #pragma unroll
            for (int fn = 0; fn < 4; fn++)
                wmma::load_matrix_sync(bf[fn], &bs[(wn*64 + fn*16) * BPITCH + kk], BPITCH);
            #pragma unroll
            for (int fm = 0; fm < 4; fm++)
                #pragma unroll
                for (int fn = 0; fn < 4; fn++)
                    wmma::mma_sync(acc[fm][fn], af[fm], bf[fn], acc[fm][fn]);
        }

        // ---- epilogue at end of each tile ----
        if ((j & 7) == 7) {
            int bn = g + 4 * (j >> 3);
            float* sc = scratch + wid * 320;
            const int colw = bn * BN + wn * 64;
            #pragma unroll
            for (int fm = 0; fm < 4; fm++) {
                float s = 0.f;
                #pragma unroll
                for (int fn = 0; fn < 4; fn++) {
                    wmma::store_matrix_sync(sc, acc[fm][fn], 20, wmma::mem_row_major);
                    wmma::fill_fragment(acc[fm][fn], 0.0f);
                    __syncwarp();
                    int c0 = colw + fn * 16 + half * 8;
                    const float* p = sc + r2 * 20 + half * 8;
                    if (c0 + 8 <= NCLS) {
                        float a0 = 0.f, a1 = 0.f;
                        #pragma unroll
                        for (int c = 0; c < 8; c += 2) {
                            a0 += __expf(S_SCALE * p[c]);
                            a1 += __expf(S_SCALE * p[c+1]);
                        }
                        s += a0 + a1;
                    } else {
                        #pragma unroll
                        for (int c = 0; c < 8; c++)
                            if (c0 + c < NCLS) s += __expf(S_SCALE * p[c]);
                    }
                    __syncwarp();
                }
                rsum[fm] += s;
            }
        }
    }

    // ---- one global atomic per row per CTA ----
    #pragma unroll
    for (int fm = 0; fm < 4; fm++) {
        float tot = rsum[fm] + __shfl_xor_sync(0xffffffffu, rsum[fm], 1);
        if (half == 0)
            atomicAdd(&g_rowsum[bm * BM + wm * 64 + fm * 16 + r2], tot);
    }
}

// ======================= kernel 4: finalize ===================================
__global__ void finalize_kernel(float* __restrict__ out) {
    __shared__ double sd[512];
    int tid = threadIdx.x;
    double local = 0.0;
    for (int i = tid; i < NROWS; i += 512) {
        float t   = g_target[i];
        float num = S_SCALE * (t - MARGIN);
        float denom = __expf(num) + g_rowsum[i] - __expf(S_SCALE * t);
        local += (double)num - (double)__logf(denom);
    }
    sd[tid] = local;
    __syncthreads();
    for (int s = 256; s > 0; s >>= 1) {
        if (tid < s) sd[tid] += sd[tid + s];
        __syncthreads();
    }
    if (tid == 0) out[0] = (float)(-sd[0] / (double)NROWS);
}

// ======================= launch ==============================================
extern "C" void kernel_launch(void* const* d_in, const int* in_sizes, int n_in,
                              void* d_out, int out_size) {
    const float* x      = (const float*)d_in[0];
    const int*   labels = (const int*)d_in[1];
    const float* W      = (const float*)d_in[2];
    float* out = (float*)d_out;

    cudaFuncSetAttribute(gemm_exp_kernel,
                         cudaFuncAttributeMaxDynamicSharedMemorySize, SMEM_BYTES);

    size_t total4 = (size_t)NCLS * DIM / 4;
    convert_w_kernel<<<(int)((total4 + 255) / 256), 256>>>(W);
    norm_target_kernel<<<NROWS, 128>>>(x, labels, W);
    {
        dim3 grid(32, 4);
        gemm_exp_kernel<<<grid, 256, SMEM_BYTES>>>();
    }
    finalize_kernel<<<1, 512>>>(out);
}

// round 5
// speedup vs baseline: 2.0684x; 1.3325x over previous
#include <cuda_runtime.h>
#include <cuda_bf16.h>
#include <cstdint>

#define NROWS 4096
#define DIM   512
#define NCLS  100000
#define NBM   32
#define NBN   391            // ceil(100000/256)
#define NTILES (NBM * NBN)   // 12512
#define GRID  148
#define S_SCALE 30.0f
#define MARGIN  0.4f

// ---------------- scratch (module-static device memory: allowed) ------------
__device__ __align__(128) __nv_bfloat16 g_WB[(size_t)NCLS * DIM];   // bf16 W
__device__ __align__(128) __nv_bfloat16 g_xn[(size_t)NROWS * DIM];  // bf16 xn
__device__ float g_rowsum[NROWS];
__device__ float g_target[NROWS];

// ---------------- tiny PTX helpers (all sm_80-era, safe on sm_103) ----------
__device__ __forceinline__ uint32_t smem_u32(const void* p) {
    uint32_t a;
    asm("{ .reg .u64 t; cvta.to.shared.u64 t, %1; cvt.u32.u64 %0, t; }" : "=r"(a) : "l"(p));
    return a;
}
#define CP_ASYNC16(dst, src) \
    asm volatile("cp.async.cg.shared.global [%0], [%1], 16;" :: "r"(dst), "l"(src) : "memory")
#define CP_COMMIT()  asm volatile("cp.async.commit_group;" ::: "memory")
#define CP_WAIT0()   asm volatile("cp.async.wait_group 0;" ::: "memory")
#define CP_WAIT1()   asm volatile("cp.async.wait_group 1;" ::: "memory")

__device__ __forceinline__ void ldsm4(uint32_t* r, uint32_t addr) {
    asm volatile("ldmatrix.sync.aligned.m8n8.x4.shared.b16 {%0,%1,%2,%3}, [%4];"
                 : "=r"(r[0]), "=r"(r[1]), "=r"(r[2]), "=r"(r[3]) : "r"(addr));
}
__device__ __forceinline__ void mma16816(float* c, const uint32_t* a,
                                         uint32_t b0, uint32_t b1) {
    asm volatile("mma.sync.aligned.m16n8k16.row.col.f32.bf16.bf16.f32 "
                 "{%0,%1,%2,%3}, {%4,%5,%6,%7}, {%8,%9}, {%0,%1,%2,%3};"
                 : "+f"(c[0]), "+f"(c[1]), "+f"(c[2]), "+f"(c[3])
                 : "r"(a[0]), "r"(a[1]), "r"(a[2]), "r"(a[3]), "r"(b0), "r"(b1));
}

// ---------------- tiling ------------------------------------------------------
#define BM 128
#define BN 256
#define BK 64
#define APITCH 520          // 1040B = 260 words == 4 mod 32 (ldsm conflict-free)
#define BPITCH 72           // 144B  = 36 words  == 4 mod 32

#define A_BYTES       (BM * APITCH * 2)              // 133120
#define B_STAGE_BYTES (BN * BPITCH * 2)              // 36864
#define B_OFF         A_BYTES
#define SMEM_BYTES    (B_OFF + 2 * B_STAGE_BYTES)    // 206848

// ======================= kernel 1: W fp32 -> bf16 ============================
__global__ void convert_w_kernel(const float* __restrict__ W) {
    size_t i = (size_t)blockIdx.x * blockDim.x + threadIdx.x;
    const size_t total = (size_t)NCLS * DIM / 4;
    if (i >= total) return;
    float4 v = reinterpret_cast<const float4*>(W)[i];
    reinterpret_cast<__nv_bfloat162*>(g_WB)[2*i+0] = __floats2bfloat162_rn(v.x, v.y);
    reinterpret_cast<__nv_bfloat162*>(g_WB)[2*i+1] = __floats2bfloat162_rn(v.z, v.w);
}

// ======================= kernel 2: normalize + exact target ==================
__device__ __forceinline__ float block_reduce_128(float v, float* sbuf, int tid) {
    #pragma unroll
    for (int o = 16; o > 0; o >>= 1) v += __shfl_xor_sync(0xffffffffu, v, o);
    if ((tid & 31) == 0) sbuf[tid >> 5] = v;
    __syncthreads();
    float r = sbuf[0] + sbuf[1] + sbuf[2] + sbuf[3];
    __syncthreads();
    return r;
}

__global__ void norm_target_kernel(const float* __restrict__ x,
                                   const int* __restrict__ labels_raw,
                                   const float* __restrict__ W) {
    __shared__ float sbuf[4];
    int row = blockIdx.x, tid = threadIdx.x;
    const float* xr = x + (size_t)row * DIM;
    float v[4]; float ss = 0.f;
    #pragma unroll
    for (int j = 0; j < 4; j++) { v[j] = xr[tid + 128*j]; ss += v[j]*v[j]; }
    ss = block_reduce_128(ss, sbuf, tid);
    float inv = rsqrtf(ss);
    #pragma unroll
    for (int j = 0; j < 4; j++)
        g_xn[(size_t)row * DIM + tid + 128*j] = __float2bfloat16(v[j] * inv);

    bool is64 = (labels_raw[1] == 0 && labels_raw[3] == 0 &&
                 labels_raw[5] == 0 && labels_raw[7] == 0);
    int lab = is64 ? labels_raw[2*row] : labels_raw[row];
    const float* w = W + (size_t)lab * DIM;
    float dot = 0.f;
    #pragma unroll
    for (int j = 0; j < 4; j++) dot += v[j] * w[tid + 128*j];
    dot = block_reduce_128(dot, sbuf, tid);
    if (tid == 0) { g_target[row] = dot * inv; g_rowsum[row] = 0.f; }
}

// ======================= kernel 3: raw-mma GEMM + exp rowsum =================
// 148 persistent CTAs over flat bm-major tile list.  Per CTA: contiguous tile
// range, segmented by bm (A strip reloaded per segment).  256 thr / 8 warps,
// warp grid 2(m) x 4(n), warp tile 64x64 as 4x8 mma.m16n8k16 accumulators.
// 2-stage cp.async pipeline, BK=64.  exp applied on accumulator registers.
__device__ __forceinline__ void issue_b_chunk(uint32_t bs_dst, int bn, int k0, int tid) {
    #pragma unroll
    for (int i = 0; i < 8; i++) {
        int v = tid + 256 * i;
        int r = v >> 3, kv = v & 7;
        int grow = bn * BN + r; if (grow >= NCLS) grow = NCLS - 1;
        const void* src = g_WB + ((size_t)grow * DIM + k0 + kv * 8);
        CP_ASYNC16(bs_dst + r * (BPITCH * 2) + kv * 16, src);
    }
}

__global__ void __launch_bounds__(256, 1) gemm_exp_kernel() {
    extern __shared__ __align__(16) char smem[];
    const uint32_t sb = smem_u32(smem);
    const int tid = threadIdx.x, wid = tid >> 5, lane = tid & 31;
    const int wm = wid & 1, wn = wid >> 1;
    const int cta = blockIdx.x;
    const int t0 = (cta * NTILES) / GRID;
    const int t1 = ((cta + 1) * NTILES) / GRID;

    // ldmatrix lane addressing: lanes 0-15 -> rows (+0..15) @k, lanes 16-31 same rows @k+8
    const int lrow = lane & 15, lk8 = (lane >> 4) << 3;
    const uint32_t a_lane = sb + ((wm * 64 + lrow) * APITCH + lk8) * 2;
    const uint32_t b_lane = sb + B_OFF + ((wn * 64 + lrow) * BPITCH + lk8) * 2;

    int t = t0;
    while (t < t1) {
        const int bm = t / NBN;
        const int bn0 = t - bm * NBN;
        const int seg_end = min(t1, (bm + 1) * NBN);
        const int total = (seg_end - t) * 8;

        __syncthreads();   // prior-segment readers done before overwriting SMEM
        // ---- A strip (once per segment) ----
        const __nv_bfloat16* xa = g_xn + (size_t)bm * BM * DIM;
        #pragma unroll 4
        for (int i = 0; i < 32; i++) {
            int v = tid + 256 * i;
            int r = v >> 6, kv = v & 63;
            CP_ASYNC16(sb + r * (APITCH * 2) + kv * 16, xa + ((size_t)r * DIM + kv * 8));
        }
        CP_COMMIT();
        issue_b_chunk(sb + B_OFF, bn0, 0, tid);
        CP_COMMIT();

        float acc[4][8][4];
        #pragma unroll
        for (int fm = 0; fm < 4; fm++)
            #pragma unroll
            for (int q = 0; q < 8; q++)
                #pragma unroll
                for (int e = 0; e < 4; e++) acc[fm][q][e] = 0.f;
        float rsum[8] = {0.f,0.f,0.f,0.f,0.f,0.f,0.f,0.f};

        for (int j = 0; j < total; j++) {
            __syncthreads();                       // stage (j+1)&1 readers done
            int jn = j + 1;
            if (jn < total) {
                issue_b_chunk(sb + B_OFF + (jn & 1) * B_STAGE_BYTES,
                              bn0 + (jn >> 3), (jn & 7) * BK, tid);
                CP_COMMIT();
                CP_WAIT1();                        // chunk j (and A) arrived
            } else {
                CP_WAIT0();                        // final chunk: full drain
            }
            __syncthreads();

            const uint32_t bch = b_lane + (j & 1) * B_STAGE_BYTES;
            const uint32_t ach = a_lane + ((j & 7) * BK) * 2;
            #pragma unroll
            for (int kk = 0; kk < BK; kk += 16) {
                uint32_t Af[4][4], Bf[4][4];
                #pragma unroll
                for (int fm = 0; fm < 4; fm++)
                    ldsm4(Af[fm], ach + (fm * 16 * APITCH + kk) * 2);
                #pragma unroll
                for (int f = 0; f < 4; f++)
                    ldsm4(Bf[f], bch + (f * 16 * BPITCH + kk) * 2);
                #pragma unroll
                for (int fm = 0; fm < 4; fm++)
                    #pragma unroll
                    for (int f = 0; f < 4; f++) {
                        mma16816(acc[fm][2*f],   Af[fm], Bf[f][0], Bf[f][2]);
                        mma16816(acc[fm][2*f+1], Af[fm], Bf[f][1], Bf[f][3]);
                    }
            }

            // ---- per-tile epilogue: exp on registers, accumulate row sums ----
            if ((j & 7) == 7) {
                const int bn = bn0 + (j >> 3);
                if (bn != NBN - 1) {
                    #pragma unroll
                    for (int fm = 0; fm < 4; fm++) {
                        float s0 = 0.f, s1 = 0.f;
                        #pragma unroll
                        for (int q = 0; q < 8; q++) {
                            s0 += __expf(S_SCALE * acc[fm][q][0]);
                            s0 += __expf(S_SCALE * acc[fm][q][1]);
                            s1 += __expf(S_SCALE * acc[fm][q][2]);
                            s1 += __expf(S_SCALE * acc[fm][q][3]);
                            acc[fm][q][0] = 0.f; acc[fm][q][1] = 0.f;
                            acc[fm][q][2] = 0.f; acc[fm][q][3] = 0.f;
                        }
                        rsum[2*fm] += s0; rsum[2*fm+1] += s1;
                    }
                } else {
                    // tail tile: cols [99840, 100096), valid local col < 160
                    const int cb = wn * 64 + (lane & 3) * 2;
                    #pragma unroll
                    for (int fm = 0; fm < 4; fm++) {
                        float s0 = 0.f, s1 = 0.f;
                        #pragma unroll
                        for (int q = 0; q < 8; q++) {
                            int c0 = cb + q * 8;
                            if (c0 < 160) {
                                s0 += __expf(S_SCALE * acc[fm][q][0]);
                                s1 += __expf(S_SCALE * acc[fm][q][2]);
                            }
                            if (c0 + 1 < 160) {
                                s0 += __expf(S_SCALE * acc[fm][q][1]);
                                s1 += __expf(S_SCALE * acc[fm][q][3]);
                            }
                            acc[fm][q][0] = 0.f; acc[fm][q][1] = 0.f;
                            acc[fm][q][2] = 0.f; acc[fm][q][3] = 0.f;
                        }
                        rsum[2*fm] += s0; rsum[2*fm+1] += s1;
                    }
                }
            }
        }

        // ---- segment flush: quad-reduce and one atomic per row ----
        #pragma unroll
        for (int k = 0; k < 8; k++) {
            float v = rsum[k];
            v += __shfl_xor_sync(0xffffffffu, v, 1);
            v += __shfl_xor_sync(0xffffffffu, v, 2);
            if ((lane & 3) == 0) {
                int row = bm * BM + wm * 64 + (k >> 1) * 16 + (lane >> 2) + (k & 1) * 8;
                atomicAdd(&g_rowsum[row], v);
            }
        }
        t = seg_end;
    }
}

// ======================= kernel 4: finalize ===================================
__global__ void finalize_kernel(float* __restrict__ out) {
    __shared__ double sd[512];
    int tid = threadIdx.x;
    double local = 0.0;
    for (int i = tid; i < NROWS; i += 512) {
        float t   = g_target[i];
        float num = S_SCALE * (t - MARGIN);
        float denom = __expf(num) + g_rowsum[i] - __expf(S_SCALE * t);
        local += (double)num - (double)__logf(denom);
    }
    sd[tid] = local;
    __syncthreads();
    for (int s = 256; s > 0; s >>= 1) {
        if (tid < s) sd[tid] += sd[tid + s];
        __syncthreads();
    }
    if (tid == 0) out[0] = (float)(-sd[0] / (double)NROWS);
}

// ======================= launch ==============================================
extern "C" void kernel_launch(void* const* d_in, const int* in_sizes, int n_in,
                              void* d_out, int out_size) {
    const float* x      = (const float*)d_in[0];
    const int*   labels = (const int*)d_in[1];
    const float* W      = (const float*)d_in[2];
    float* out = (float*)d_out;

    cudaFuncSetAttribute(gemm_exp_kernel,
                         cudaFuncAttributeMaxDynamicSharedMemorySize, SMEM_BYTES);

    size_t total4 = (size_t)NCLS * DIM / 4;
    convert_w_kernel<<<(int)((total4 + 255) / 256), 256>>>(W);
    norm_target_kernel<<<NROWS, 128>>>(x, labels, W);
    gemm_exp_kernel<<<GRID, 256, SMEM_BYTES>>>();
    finalize_kernel<<<1, 512>>>(out);
}

// round 6
// speedup vs baseline: 2.2817x; 1.1031x over previous
#include <cuda_runtime.h>
#include <cuda_bf16.h>
#include <cuda_fp8.h>
#include <cstdint>

#define NROWS 4096
#define DIM   512
#define NCLS  100000
#define NBM   32
#define NBN   391            // ceil(100000/256)
#define NTILES (NBM * NBN)   // 12512
#define GRID  148
#define S_SCALE 30.0f
#define MARGIN  0.4f
#define XS 8.0f              // fp8 scale for xn
#define WS 32.0f             // fp8 scale for W
#define EXPS (S_SCALE / (XS * WS))   // exp arg multiplier on raw acc

// ---------------- scratch (module-static device memory: allowed) ------------
__device__ __align__(128) uint8_t g_WB8[(size_t)NCLS * DIM];   // e4m3 W*32
__device__ __align__(128) uint8_t g_xn8[(size_t)NROWS * DIM];  // e4m3 xn*8
__device__ float g_rowsum[NROWS];
__device__ float g_target[NROWS];

// ---------------- PTX helpers (sm_80/89-era, safe on sm_103) ----------------
__device__ __forceinline__ uint32_t smem_u32(const void* p) {
    uint32_t a;
    asm("{ .reg .u64 t; cvta.to.shared.u64 t, %1; cvt.u32.u64 %0, t; }" : "=r"(a) : "l"(p));
    return a;
}
#define CP_ASYNC16(dst, src) \
    asm volatile("cp.async.cg.shared.global [%0], [%1], 16;" :: "r"(dst), "l"(src) : "memory")
#define CP_COMMIT()  asm volatile("cp.async.commit_group;" ::: "memory")
#define CP_WAIT0()   asm volatile("cp.async.wait_group 0;" ::: "memory")
#define CP_WAIT1()   asm volatile("cp.async.wait_group 1;" ::: "memory")

__device__ __forceinline__ void ldsm4(uint32_t* r, uint32_t addr) {
    asm volatile("ldmatrix.sync.aligned.m8n8.x4.shared.b16 {%0,%1,%2,%3}, [%4];"
                 : "=r"(r[0]), "=r"(r[1]), "=r"(r[2]), "=r"(r[3]) : "r"(addr));
}
// e4m3 MMA: m16n8k32, fp32 accum.  Fragment bytes are isomorphic to bf16 k16.
__device__ __forceinline__ void mma_fp8(float* c, const uint32_t* a,
                                        uint32_t b0, uint32_t b1) {
    asm volatile("mma.sync.aligned.m16n8k32.row.col.f32.e4m3.e4m3.f32 "
                 "{%0,%1,%2,%3}, {%4,%5,%6,%7}, {%8,%9}, {%0,%1,%2,%3};"
                 : "+f"(c[0]), "+f"(c[1]), "+f"(c[2]), "+f"(c[3])
                 : "r"(a[0]), "r"(a[1]), "r"(a[2]), "r"(a[3]), "r"(b0), "r"(b1));
}
__device__ __forceinline__ uint32_t pack4_e4m3(float a0, float a1, float a2, float a3) {
    __nv_fp8x2_e4m3 lo(make_float2(a0, a1));
    __nv_fp8x2_e4m3 hi(make_float2(a2, a3));
    return (uint32_t)lo.__x | ((uint32_t)hi.__x << 16);
}

// ---------------- tiling (all pitches in BYTES) -------------------------------
#define BM 128
#define BN 256
#define CHUNK_B 128          // bytes of K per pipeline chunk (= 128 fp8 elems)
#define NCHUNK  4            // DIM*1B / CHUNK_B
#define APITCH 528           // 132 words == 4 mod 32 (ldsm conflict-free)
#define BPITCH 144           // 36 words  == 4 mod 32

#define A_BYTES       (BM * APITCH)                  // 67584
#define B_STAGE_BYTES (BN * BPITCH)                  // 36864
#define B_OFF         A_BYTES
#define SMEM_BYTES    (B_OFF + 2 * B_STAGE_BYTES)    // 141312

// ======================= kernel 1: prep (fused convert + normalize) ==========
// blocks [0, NROWS): row normalize + exact fp32 target + fp8 xn
// blocks [NROWS, NROWS+25000): W fp32 -> e4m3*32   (128 thr * 16 elems = 2048/blk)
__device__ __forceinline__ float block_reduce_128(float v, float* sbuf, int tid) {
    #pragma unroll
    for (int o = 16; o > 0; o >>= 1) v += __shfl_xor_sync(0xffffffffu, v, o);
    if ((tid & 31) == 0) sbuf[tid >> 5] = v;
    __syncthreads();
    float r = sbuf[0] + sbuf[1] + sbuf[2] + sbuf[3];
    __syncthreads();
    return r;
}

__global__ void prep_kernel(const float* __restrict__ x,
                            const int* __restrict__ labels_raw,
                            const float* __restrict__ W) {
    __shared__ float sbuf[4];
    const int tid = threadIdx.x;
    if (blockIdx.x < NROWS) {
        const int row = blockIdx.x;
        const float* xr = x + (size_t)row * DIM;
        float v[4]; float ss = 0.f;
        #pragma unroll
        for (int j = 0; j < 4; j++) { v[j] = xr[tid + 128*j]; ss += v[j]*v[j]; }
        ss = block_reduce_128(ss, sbuf, tid);
        float inv = rsqrtf(ss);
        #pragma unroll
        for (int j = 0; j < 4; j++)
            g_xn8[(size_t)row * DIM + tid + 128*j] =
                __nv_fp8_e4m3(v[j] * inv * XS).__x;

        bool is64 = (labels_raw[1] == 0 && labels_raw[3] == 0 &&
                     labels_raw[5] == 0 && labels_raw[7] == 0);
        int lab = is64 ? labels_raw[2*row] : labels_raw[row];
        const float* w = W + (size_t)lab * DIM;
        float dot = 0.f;
        #pragma unroll
        for (int j = 0; j < 4; j++) dot += v[j] * w[tid + 128*j];
        dot = block_reduce_128(dot, sbuf, tid);
        if (tid == 0) { g_target[row] = dot * inv; g_rowsum[row] = 0.f; }
    } else {
        const size_t base = ((size_t)(blockIdx.x - NROWS) * 128 + tid) * 16;
        const float4* src = reinterpret_cast<const float4*>(W + base);
        float4 v0 = src[0], v1 = src[1], v2 = src[2], v3 = src[3];
        uint4 o;
        o.x = pack4_e4m3(v0.x*WS, v0.y*WS, v0.z*WS, v0.w*WS);
        o.y = pack4_e4m3(v1.x*WS, v1.y*WS, v1.z*WS, v1.w*WS);
        o.z = pack4_e4m3(v2.x*WS, v2.y*WS, v2.z*WS, v2.w*WS);
        o.w = pack4_e4m3(v3.x*WS, v3.y*WS, v3.z*WS, v3.w*WS);
        *reinterpret_cast<uint4*>(g_WB8 + base) = o;
    }
}

// ======================= kernel 2: fp8-mma GEMM + exp rowsum =================
// 148 persistent CTAs, flat bm-major tile list, persistent A strip per segment.
// 256 thr / 8 warps, warp grid 2(m) x 4(n), warp tile 64x64 via m16n8k32 e4m3.
// 2-stage cp.async pipeline, 128B K-chunks (4 per tile).
__device__ __forceinline__ void issue_b_chunk(uint32_t bs_dst, int bn, int k0, int tid) {
    #pragma unroll
    for (int i = 0; i < 8; i++) {
        int v = tid + 256 * i;                  // 2048 vectors = 256 rows x 8
        int r = v >> 3, kv = v & 7;
        int grow = bn * BN + r; if (grow >= NCLS) grow = NCLS - 1;
        const void* src = g_WB8 + ((size_t)grow * DIM + k0 + kv * 16);
        CP_ASYNC16(bs_dst + r * BPITCH + kv * 16, src);
    }
}

__global__ void __launch_bounds__(256, 1) gemm_exp_kernel() {
    extern __shared__ __align__(16) char smem[];
    const uint32_t sb = smem_u32(smem);
    const int tid = threadIdx.x, wid = tid >> 5, lane = tid & 31;
    const int wm = wid & 1, wn = wid >> 1;
    const int cta = blockIdx.x;
    const int t0 = (cta * NTILES) / GRID;
    const int t1 = ((cta + 1) * NTILES) / GRID;

    const int lrow = lane & 15, lk16 = (lane >> 4) * 16;
    const uint32_t a_lane = sb + (wm * 64 + lrow) * APITCH + lk16;
    const uint32_t b_lane = sb + B_OFF + (wn * 64 + lrow) * BPITCH + lk16;

    int t = t0;
    while (t < t1) {
        const int bm = t / NBN;
        const int bn0 = t - bm * NBN;
        const int seg_end = min(t1, (bm + 1) * NBN);
        const int total = (seg_end - t) * NCHUNK;

        __syncthreads();   // prior-segment readers done before overwriting SMEM
        // ---- A strip (once per segment): 128 rows x 512 B ----
        const uint8_t* xa = g_xn8 + (size_t)bm * BM * DIM;
        #pragma unroll 4
        for (int i = 0; i < 16; i++) {
            int v = tid + 256 * i;              // 4096 vectors = 128 rows x 32
            int r = v >> 5, kv = v & 31;
            CP_ASYNC16(sb + r * APITCH + kv * 16, xa + ((size_t)r * DIM + kv * 16));
        }
        CP_COMMIT();
        issue_b_chunk(sb + B_OFF, bn0, 0, tid);
        CP_COMMIT();

        float acc[4][8][4];
        #pragma unroll
        for (int fm = 0; fm < 4; fm++)
            #pragma unroll
            for (int q = 0; q < 8; q++)
                #pragma unroll
                for (int e = 0; e < 4; e++) acc[fm][q][e] = 0.f;
        float rsum[8] = {0.f,0.f,0.f,0.f,0.f,0.f,0.f,0.f};

        for (int j = 0; j < total; j++) {
            __syncthreads();
            int jn = j + 1;
            if (jn < total) {
                issue_b_chunk(sb + B_OFF + (jn & 1) * B_STAGE_BYTES,
                              bn0 + (jn >> 2), (jn & 3) * CHUNK_B, tid);
                CP_COMMIT();
                CP_WAIT1();
            } else {
                CP_WAIT0();
            }
            __syncthreads();

            const uint32_t bch = b_lane + (j & 1) * B_STAGE_BYTES;
            const uint32_t ach = a_lane + (j & 3) * CHUNK_B;
            #pragma unroll
            for (int ks = 0; ks < 4; ks++) {      // 4 x k32 per 128B chunk
                uint32_t Af[4][4], Bf[4][4];
                #pragma unroll
                for (int fm = 0; fm < 4; fm++)
                    ldsm4(Af[fm], ach + fm * 16 * APITCH + ks * 32);
                #pragma unroll
                for (int f = 0; f < 4; f++)
                    ldsm4(Bf[f], bch + f * 16 * BPITCH + ks * 32);
                #pragma unroll
                for (int fm = 0; fm < 4; fm++)
                    #pragma unroll
                    for (int f = 0; f < 4; f++) {
                        mma_fp8(acc[fm][2*f],   Af[fm], Bf[f][0], Bf[f][2]);
                        mma_fp8(acc[fm][2*f+1], Af[fm], Bf[f][1], Bf[f][3]);
                    }
            }

            // ---- per-tile epilogue: exp on accumulator registers ----
            if ((j & 3) == 3) {
                const int bn = bn0 + (j >> 2);
                if (bn != NBN - 1) {
                    #pragma unroll
                    for (int fm = 0; fm < 4; fm++) {
                        float s0 = 0.f, s1 = 0.f;
                        #pragma unroll
                        for (int q = 0; q < 8; q++) {
                            s0 += __expf(EXPS * acc[fm][q][0]);
                            s0 += __expf(EXPS * acc[fm][q][1]);
                            s1 += __expf(EXPS * acc[fm][q][2]);
                            s1 += __expf(EXPS * acc[fm][q][3]);
                            acc[fm][q][0] = 0.f; acc[fm][q][1] = 0.f;
                            acc[fm][q][2] = 0.f; acc[fm][q][3] = 0.f;
                        }
                        rsum[2*fm] += s0; rsum[2*fm+1] += s1;
                    }
                } else {
                    // tail tile: cols [99840, 100096), valid local col < 160
                    const int cb = wn * 64 + (lane & 3) * 2;
                    #pragma unroll
                    for (int fm = 0; fm < 4; fm++) {
                        float s0 = 0.f, s1 = 0.f;
                        #pragma unroll
                        for (int q = 0; q < 8; q++) {
                            int c0 = cb + q * 8;
                            if (c0 < 160) {
                                s0 += __expf(EXPS * acc[fm][q][0]);
                                s1 += __expf(EXPS * acc[fm][q][2]);
                            }
                            if (c0 + 1 < 160) {
                                s0 += __expf(EXPS * acc[fm][q][1]);
                                s1 += __expf(EXPS * acc[fm][q][3]);
                            }
                            acc[fm][q][0] = 0.f; acc[fm][q][1] = 0.f;
                            acc[fm][q][2] = 0.f; acc[fm][q][3] = 0.f;
                        }
                        rsum[2*fm] += s0; rsum[2*fm+1] += s1;
                    }
                }
            }
        }

        // ---- segment flush: quad-reduce, one atomic per row ----
        #pragma unroll
        for (int k = 0; k < 8; k++) {
            float v = rsum[k];
            v += __shfl_xor_sync(0xffffffffu, v, 1);
            v += __shfl_xor_sync(0xffffffffu, v, 2);
            if ((lane & 3) == 0) {
                int row = bm * BM + wm * 64 + (k >> 1) * 16 + (lane >> 2) + (k & 1) * 8;
                atomicAdd(&g_rowsum[row], v);
            }
        }
        t = seg_end;
    }
}

// ======================= kernel 3: finalize ===================================
__global__ void finalize_kernel(float* __restrict__ out) {
    __shared__ double sd[512];
    int tid = threadIdx.x;
    double local = 0.0;
    for (int i = tid; i < NROWS; i += 512) {
        float t   = g_target[i];
        float num = S_SCALE * (t - MARGIN);
        float denom = __expf(num) + g_rowsum[i] - __expf(S_SCALE * t);
        local += (double)num - (double)__logf(denom);
    }
    sd[tid] = local;
    __syncthreads();
    for (int s = 256; s > 0; s >>= 1) {
        if (tid < s) sd[tid] += sd[tid + s];
        __syncthreads();
    }
    if (tid == 0) out[0] = (float)(-sd[0] / (double)NROWS);
}

// ======================= launch ==============================================
extern "C" void kernel_launch(void* const* d_in, const int* in_sizes, int n_in,
                              void* d_out, int out_size) {
    const float* x      = (const float*)d_in[0];
    const int*   labels = (const int*)d_in[1];
    const float* W      = (const float*)d_in[2];
    float* out = (float*)d_out;

    cudaFuncSetAttribute(gemm_exp_kernel,
                         cudaFuncAttributeMaxDynamicSharedMemorySize, SMEM_BYTES);

    // 4096 norm blocks + 25000 W-convert blocks (128 thr x 16 elems each)
    prep_kernel<<<NROWS + 25000, 128>>>(x, labels, W);
    gemm_exp_kernel<<<GRID, 256, SMEM_BYTES>>>();
    finalize_kernel<<<1, 512>>>(out);
}